// round 12
// baseline (speedup 1.0000x reference)
#include <cuda_runtime.h>
#include <cstdint>

#define BS 4
#define SQ 1024
#define CH 64
#define UN 32
#define TSPAN 72
#define GRID (BS * 128)

__device__ float g_k[BS * SQ * UN];
__device__ unsigned g_flag[GRID];   // monotonic; +9 per block per launch

__device__ __forceinline__ float htanh(float x) {
    float y;
    asm("tanh.approx.f32 %0, %1;" : "=f"(y) : "f"(x));
    return y;
}

// shared pool (floats)
#define OFF_XTS  0                    // xts [72][68] = 4896
#define OFF_U1   4896                 // ph1: wts[32][68]+wxs[32][68]=4352
                                      // ph2: ks[72][36]=2592 + vs 2208 = 4800
#define OFF_QS   (4896 + 4800)        // qs [8][32] = 256
#define OFF_AS   (OFF_QS + 256)       // a_s [8][64] = 512
#define OFF_WAS  (OFF_AS + 512)       // 32
#define OFF_SUM  (OFF_WAS + 32)       // 16
#define SMEM_FLOATS (OFF_SUM + 16)

__global__ __launch_bounds__(512, 4) void fused_kernel(
    const float* __restrict__ x,
    const float* __restrict__ Wt,
    const float* __restrict__ Wx,
    const float* __restrict__ bh,
    const float* __restrict__ wa,
    float* __restrict__ vout,
    float* __restrict__ aout)
{
    __shared__ __align__(16) float pool[SMEM_FLOATS];

    float* xts  = pool + OFF_XTS;   // [ti][c-swizzled], stride 68
    float* qs   = pool + OFF_QS;    // [r][u]
    float* was  = pool + OFF_WAS;
    float* sumb = pool + OFF_SUM;   // [r*2+h]

    int b = blockIdx.x >> 7;
    int sblk = blockIdx.x & 127;
    int s0 = sblk << 3;
    int tid = threadIdx.x;
    int wid = tid >> 5, ln = tid & 31;
    int r = wid >> 1;               // query row in block
    int h = wid & 1;                // window half
    int s = s0 + r;
    int tlo = s0 - 32;

    // ---- top: zero-fill the ENTIRE a row; the scalar value store below is
    //      ordered by the intervening __syncthreads (block-scope fence) ----
    float4 z4 = make_float4(0.f, 0.f, 0.f, 0.f);
    float4* arow = (float4*)(aout + (((size_t)b * SQ + s) << 10));
#pragma unroll
    for (int i = 0; i < 4; i++)
        arow[(h << 7) + (i << 5) + ln] = z4;

    // ---- top: one LDG wave -- w tiles + xts halo + was ----
    {
        float* wts = pool + OFF_U1;          // [u][c], stride 68
        float* wxs = wts + UN * 68;
        int u = tid >> 4, g = tid & 15;      // 512 = 32u x 16 groups
        *(float4*)&wts[u * 68 + g * 4] = ((const float4*)Wt)[tid];
        *(float4*)&wxs[u * 68 + g * 4] = ((const float4*)Wx)[tid];
        if (tid < UN) was[tid] = wa[tid];

        int cc = tid >> 3, gq = tid & 7;
        int gb = cc >> 2, clo = cc & 3;
        const float* xb = x + (size_t)b * CH * SQ + cc * SQ;
        if (sblk >= 4 && sblk <= 123) {
            const float4* xb4 = (const float4*)(xb + tlo);   // tlo % 4 == 0
#pragma unroll
            for (int f = 0; f < 3; f++) {
                int fi = gq + f * 8;
                if (fi < 18) {
                    float4 v = xb4[fi];
                    int t0 = fi << 2;
                    xts[(t0 + 0) * 68 + (((((t0 + 0) & 7) ^ gb) << 2) | clo)] = v.x;
                    xts[(t0 + 1) * 68 + (((((t0 + 1) & 7) ^ gb) << 2) | clo)] = v.y;
                    xts[(t0 + 2) * 68 + (((((t0 + 2) & 7) ^ gb) << 2) | clo)] = v.z;
                    xts[(t0 + 3) * 68 + (((((t0 + 3) & 7) ^ gb) << 2) | clo)] = v.w;
                }
            }
        } else {
#pragma unroll
            for (int p = 0; p < 9; p++) {
                int ti = p * 8 + gq;
                int tc = min(max(tlo + ti, 0), SQ - 1);
                int csw = ((gb ^ gq) << 2) | clo;   // ti&7 == gq
                xts[ti * 68 + csw] = xb[tc];
            }
        }
    }
    __syncthreads();                         // SYNC_A

    // ---- phase 1: q (warps 0-7) / k (warps 8-15), x rows from xts ----
    {
        const float* wts = pool + OFF_U1;
        const float* wxs = wts + UN * 68;
        int ss = wid & 7;                    // own row index
        const float* wrow = (tid < 256) ? &wts[ln * 68] : &wxs[ln * 68];
        const float4* xp = (const float4*)&xts[(32 + ss) * 68];
        float a0 = 0.f, a1 = 0.f, a2 = 0.f, a3 = 0.f;
#pragma unroll
        for (int gg = 0; gg < 16; gg++) {    // gg = stored (swizzled) group
            float4 x4 = xp[gg];
            int wg = (gg & 8) | ((gg & 7) ^ ss);   // original channel group
            float4 w4 = *(const float4*)&wrow[wg * 4];
            a0 = fmaf(x4.x, w4.x, a0); a1 = fmaf(x4.y, w4.y, a1);
            a2 = fmaf(x4.z, w4.z, a2); a3 = fmaf(x4.w, w4.w, a3);
        }
        float res = (a0 + a1) + (a2 + a3);
        if (tid < 256) {
            qs[ss * 32 + ln] = res;
        } else {
            g_k[((size_t)b * SQ + s0 + ss) * UN + ln] = res + bh[ln];  // bh folded
        }
    }
    __syncthreads();                         // SYNC_B: k stored, wts free

    // ---- release + per-warp neighbor spin + ks fill (warps 0..8) ----
    float* ks = pool + OFF_U1;               // [ti][u], stride 36 (odd 16B units)
    if (wid <= 8) {
        if (ln == 0) {
            __threadfence();                 // release own k stores
            unsigned v = atomicAdd(&g_flag[blockIdx.x], 1u);
            unsigned base = v - (v % 9u);    // 9*(launchN-1)
            int owner = min(max(sblk - 4 + wid, 0), 127);
            volatile unsigned* f = (volatile unsigned*)&g_flag[(b << 7) + owner];
            while (*f <= base) { }
            __threadfence();                 // acquire
        }
        __syncwarp();
        const float4* gk4 = (const float4*)g_k;
#pragma unroll
        for (int rep = 0; rep < 2; rep++) {
            int lin = ln + (rep << 5);       // 0..63
            int ti = (wid << 3) + (lin >> 3);
            int gq = lin & 7;
            int tc = min(max(tlo + ti, 0), SQ - 1);
            *(float4*)&ks[ti * 36 + gq * 4] = gk4[((size_t)b * SQ + tc) * 8 + gq];
        }
    }
    __syncthreads();                         // SYNC_D: ks ready

    // ---- scores (2 independent FMA chains) + softmax (no max-shift) ----
    int j = h * 32 + ln;
    int t = s - 32 + j;
    bool valid = (t >= 0) && (t < SQ);
    int ti = r + j;                          // <= 70

    const float4* kp = (const float4*)&ks[ti * 36];
    const float4* qp = (const float4*)&qs[r * 32];
    const float4* wap = (const float4*)was;
    float acc0 = 0.f, acc1 = 0.f;
#pragma unroll
    for (int g = 0; g < 8; g++) {
        float4 q4 = qp[g];
        float4 w4 = wap[g];
        float4 k4 = kp[g];
        acc0 = fmaf(w4.x, htanh(q4.x + k4.x), acc0);
        acc1 = fmaf(w4.y, htanh(q4.y + k4.y), acc1);
        acc0 = fmaf(w4.z, htanh(q4.z + k4.z), acc0);
        acc1 = fmaf(w4.w, htanh(q4.w + k4.w), acc1);
    }
    float acc = acc0 + acc1;

    float* a_s = pool + OFF_AS;
    float e = valid ? __expf(acc) : 0.f;
    float sm = e;
#pragma unroll
    for (int o = 16; o > 0; o >>= 1) sm += __shfl_xor_sync(0xffffffffu, sm, o);
    if (ln == 0) sumb[r * 2 + h] = sm;
    a_s[(r << 6) + j] = e;                   // unnormalized (v-pass input)
    __syncthreads();                         // SYNC_E

    float inv = __fdividef(1.f, sumb[r * 2] + sumb[r * 2 + 1] + 1e-7f);

    // ---- a window write: ONE predicated scalar STG per lane (coalesced) ----
    if (valid)
        aout[(((size_t)b * SQ + s) << 10) + t] = e * inv;

    // ---- v pass: 16 c-groups x 4 j-segments per row ----
    float* vs = pool + OFF_U1 + 2592;        // staggered: f(pseg)=pseg*68+r*4
    {
        int q64 = tid & 63;
        int cgrp = q64 & 15;
        int jseg = q64 >> 4;
        float4 vacc = z4;
#pragma unroll
        for (int it2 = 0; it2 < 4; it2++) {
            float4 a4 = *(const float4*)&a_s[(r << 6) + (jseg << 4) + (it2 << 2)];
            int jb = (jseg << 4) + (it2 << 2);
#pragma unroll
            for (int ee = 0; ee < 4; ee++) {
                int row = r + jb + ee;
                float av = (ee == 0) ? a4.x : (ee == 1) ? a4.y : (ee == 2) ? a4.z : a4.w;
                float4 x4 = *(const float4*)&xts[row * 68 + ((cgrp ^ (row & 7)) << 2)];
                vacc.x = fmaf(av, x4.x, vacc.x);
                vacc.y = fmaf(av, x4.y, vacc.y);
                vacc.z = fmaf(av, x4.z, vacc.z);
                vacc.w = fmaf(av, x4.w, vacc.w);
            }
        }
        vacc.x *= inv; vacc.y *= inv; vacc.z *= inv; vacc.w *= inv;
        int pseg = (r << 2) + jseg;
        *(float4*)&vs[pseg * 68 + (r << 2) + (cgrp << 2)] = vacc;
    }
    __syncthreads();                         // SYNC_F

    // ---- combine 4 j-segment partials (conflict-free banks) + v write ----
    {
        int c = tid >> 3, i = tid & 7;
        int base = (i * 4) * 68 + i * 4 + c;
        float vsum = (vs[base] + vs[base + 68]) +
                     (vs[base + 136] + vs[base + 204]);
        vout[(size_t)b * CH * SQ + c * SQ + s0 + i] = vsum;
    }
}

extern "C" void kernel_launch(void* const* d_in, const int* in_sizes, int n_in,
                              void* d_out, int out_size) {
    (void)in_sizes; (void)n_in; (void)out_size;
    const float* x  = (const float*)d_in[0];
    const float* Wt = (const float*)d_in[1];
    const float* Wx = (const float*)d_in[2];
    const float* Wa = (const float*)d_in[3];
    // d_in[4] = Wa_b: cancels exactly in the softmax, unused
    const float* bh = (const float*)d_in[5];

    float* vout = (float*)d_out;                     // (B, C, S)
    float* aout = vout + (size_t)BS * CH * SQ;       // (B, S, S)

    fused_kernel<<<GRID, 512>>>(x, Wt, Wx, bh, Wa, vout, aout);
}

// round 13
// speedup vs baseline: 1.0950x; 1.0950x over previous
#include <cuda_runtime.h>
#include <cstdint>

#define BS 4
#define SQ 1024
#define CH 64
#define UN 32
#define TSPAN 72
#define GRID (BS * 128)

__device__ float g_k[BS * SQ * UN];
__device__ unsigned g_flag[GRID];   // monotonic; +9 per block per launch

__device__ __forceinline__ float htanh(float x) {
    float y;
    asm("tanh.approx.f32 %0, %1;" : "=f"(y) : "f"(x));
    return y;
}

// shared pool (floats)
#define OFF_XTS  0                    // xts [72][68] = 4896
#define OFF_U1   4896                 // ph1: wts[32][68]+wxs[32][68]=4352
                                      // ph2: ks[72][36]=2592 + vs 2208 = 4800
#define OFF_QS   (4896 + 4800)        // qs [8][32] = 256
#define OFF_AS   (OFF_QS + 256)       // a_s [8][64] = 512
#define OFF_WAS  (OFF_AS + 512)       // 32
#define OFF_SUM  (OFF_WAS + 32)       // 16
#define SMEM_FLOATS (OFF_SUM + 16)

__global__ __launch_bounds__(512, 4) void fused_kernel(
    const float* __restrict__ x,
    const float* __restrict__ Wt,
    const float* __restrict__ Wx,
    const float* __restrict__ bh,
    const float* __restrict__ wa,
    float* __restrict__ vout,
    float* __restrict__ aout)
{
    __shared__ __align__(16) float pool[SMEM_FLOATS];

    float* xts  = pool + OFF_XTS;   // [ti][c-swizzled], stride 68
    float* qs   = pool + OFF_QS;    // [r][u]
    float* was  = pool + OFF_WAS;
    float* sumb = pool + OFF_SUM;   // [r*2+h]

    int b = blockIdx.x >> 7;
    int sblk = blockIdx.x & 127;
    int s0 = sblk << 3;
    int tid = threadIdx.x;
    int wid = tid >> 5, ln = tid & 31;
    int r = wid >> 1;               // query row in block
    int h = wid & 1;                // window half
    int s = s0 + r;
    int tlo = s0 - 32;

    // ---- top: ONLY the input LDG wave (critical path to flag release) ----
    {
        float* wts = pool + OFF_U1;          // [u][c], stride 68
        float* wxs = wts + UN * 68;
        int u = tid >> 4, g = tid & 15;      // 512 = 32u x 16 groups
        *(float4*)&wts[u * 68 + g * 4] = ((const float4*)Wt)[tid];
        *(float4*)&wxs[u * 68 + g * 4] = ((const float4*)Wx)[tid];
        if (tid < UN) was[tid] = wa[tid];

        int cc = tid >> 3, gq = tid & 7;
        int gb = cc >> 2, clo = cc & 3;
        const float* xb = x + (size_t)b * CH * SQ + cc * SQ;
        if (sblk >= 4 && sblk <= 123) {
            const float4* xb4 = (const float4*)(xb + tlo);   // tlo % 4 == 0
#pragma unroll
            for (int f = 0; f < 3; f++) {
                int fi = gq + f * 8;
                if (fi < 18) {
                    float4 v = xb4[fi];
                    int t0 = fi << 2;
                    xts[(t0 + 0) * 68 + (((((t0 + 0) & 7) ^ gb) << 2) | clo)] = v.x;
                    xts[(t0 + 1) * 68 + (((((t0 + 1) & 7) ^ gb) << 2) | clo)] = v.y;
                    xts[(t0 + 2) * 68 + (((((t0 + 2) & 7) ^ gb) << 2) | clo)] = v.z;
                    xts[(t0 + 3) * 68 + (((((t0 + 3) & 7) ^ gb) << 2) | clo)] = v.w;
                }
            }
        } else {
#pragma unroll
            for (int p = 0; p < 9; p++) {
                int ti = p * 8 + gq;
                int tc = min(max(tlo + ti, 0), SQ - 1);
                int csw = ((gb ^ gq) << 2) | clo;   // ti&7 == gq
                xts[ti * 68 + csw] = xb[tc];
            }
        }
    }
    __syncthreads();                         // SYNC_A

    // ---- phase 1: q (warps 0-7) / k (warps 8-15), x rows from xts ----
    {
        const float* wts = pool + OFF_U1;
        const float* wxs = wts + UN * 68;
        int ss = wid & 7;                    // own row index
        const float* wrow = (tid < 256) ? &wts[ln * 68] : &wxs[ln * 68];
        const float4* xp = (const float4*)&xts[(32 + ss) * 68];
        float a0 = 0.f, a1 = 0.f, a2 = 0.f, a3 = 0.f;
#pragma unroll
        for (int gg = 0; gg < 16; gg++) {    // gg = stored (swizzled) group
            float4 x4 = xp[gg];
            int wg = (gg & 8) | ((gg & 7) ^ ss);   // original channel group
            float4 w4 = *(const float4*)&wrow[wg * 4];
            a0 = fmaf(x4.x, w4.x, a0); a1 = fmaf(x4.y, w4.y, a1);
            a2 = fmaf(x4.z, w4.z, a2); a3 = fmaf(x4.w, w4.w, a3);
        }
        float res = (a0 + a1) + (a2 + a3);
        if (tid < 256) {
            qs[ss * 32 + ln] = res;
        } else {
            g_k[((size_t)b * SQ + s0 + ss) * UN + ln] = res + bh[ln];  // bh folded
        }
    }
    __syncthreads();                         // SYNC_B: k stored, wts free

    // ---- warps 0-8: release + neighbor spin + ks fill.
    //      warps 9-15: zero-fill the a rows (off the critical path). ----
    float* ks = pool + OFF_U1;               // [ti][u], stride 36 (odd 16B units)
    if (wid <= 8) {
        if (ln == 0) {
            __threadfence();                 // release own k stores
            unsigned v = atomicAdd(&g_flag[blockIdx.x], 1u);
            unsigned base = v - (v % 9u);    // 9*(launchN-1)
            int owner = min(max(sblk - 4 + wid, 0), 127);
            volatile unsigned* f = (volatile unsigned*)&g_flag[(b << 7) + owner];
            while (*f <= base) { }
            __threadfence();                 // acquire
        }
        __syncwarp();
        const float4* gk4 = (const float4*)g_k;
#pragma unroll
        for (int rep = 0; rep < 2; rep++) {
            int lin = ln + (rep << 5);       // 0..63
            int ti = (wid << 3) + (lin >> 3);
            int gq = lin & 7;
            int tc = min(max(tlo + ti, 0), SQ - 1);
            *(float4*)&ks[ti * 36 + gq * 4] = gk4[((size_t)b * SQ + tc) * 8 + gq];
        }
    } else {
        // zero all 8 a-rows: 8*256 float4 = 2048 stores over 224 lanes
        float4 zz = make_float4(0.f, 0.f, 0.f, 0.f);
        float4* abase = (float4*)(aout + (((size_t)b * SQ + s0) << 10));
        for (int idx = tid - 288; idx < 2048; idx += 224)
            abase[idx] = zz;                 // row = idx>>8 (contiguous rows)
    }
    __syncthreads();                         // SYNC_D: ks ready, zeros issued

    // ---- scores (2 independent FMA chains) + softmax (no max-shift) ----
    int j = h * 32 + ln;
    int t = s - 32 + j;
    bool valid = (t >= 0) && (t < SQ);
    int ti = r + j;                          // <= 70

    const float4* kp = (const float4*)&ks[ti * 36];
    const float4* qp = (const float4*)&qs[r * 32];
    const float4* wap = (const float4*)was;
    float acc0 = 0.f, acc1 = 0.f;
#pragma unroll
    for (int g = 0; g < 8; g++) {
        float4 q4 = qp[g];
        float4 w4 = wap[g];
        float4 k4 = kp[g];
        acc0 = fmaf(w4.x, htanh(q4.x + k4.x), acc0);
        acc1 = fmaf(w4.y, htanh(q4.y + k4.y), acc1);
        acc0 = fmaf(w4.z, htanh(q4.z + k4.z), acc0);
        acc1 = fmaf(w4.w, htanh(q4.w + k4.w), acc1);
    }
    float acc = acc0 + acc1;

    float* a_s = pool + OFF_AS;
    float e = valid ? __expf(acc) : 0.f;
    float sm = e;
#pragma unroll
    for (int o = 16; o > 0; o >>= 1) sm += __shfl_xor_sync(0xffffffffu, sm, o);
    if (ln == 0) sumb[r * 2 + h] = sm;
    a_s[(r << 6) + j] = e;                   // unnormalized (v-pass input)
    __syncthreads();                         // SYNC_E

    float inv = __fdividef(1.f, sumb[r * 2] + sumb[r * 2 + 1] + 1e-7f);

    // ---- a window write: ONE predicated scalar STG per lane (coalesced);
    //      ordered after the zero wave by SYNC_D + SYNC_E ----
    if (valid)
        aout[(((size_t)b * SQ + s) << 10) + t] = e * inv;

    // ---- v pass: 16 c-groups x 4 j-segments per row ----
    float* vs = pool + OFF_U1 + 2592;        // staggered: f(pseg)=pseg*68+r*4
    {
        int q64 = tid & 63;
        int cgrp = q64 & 15;
        int jseg = q64 >> 4;
        float4 vacc = make_float4(0.f, 0.f, 0.f, 0.f);
#pragma unroll
        for (int it2 = 0; it2 < 4; it2++) {
            float4 a4 = *(const float4*)&a_s[(r << 6) + (jseg << 4) + (it2 << 2)];
            int jb = (jseg << 4) + (it2 << 2);
#pragma unroll
            for (int ee = 0; ee < 4; ee++) {
                int row = r + jb + ee;
                float av = (ee == 0) ? a4.x : (ee == 1) ? a4.y : (ee == 2) ? a4.z : a4.w;
                float4 x4 = *(const float4*)&xts[row * 68 + ((cgrp ^ (row & 7)) << 2)];
                vacc.x = fmaf(av, x4.x, vacc.x);
                vacc.y = fmaf(av, x4.y, vacc.y);
                vacc.z = fmaf(av, x4.z, vacc.z);
                vacc.w = fmaf(av, x4.w, vacc.w);
            }
        }
        vacc.x *= inv; vacc.y *= inv; vacc.z *= inv; vacc.w *= inv;
        int pseg = (r << 2) + jseg;
        *(float4*)&vs[pseg * 68 + (r << 2) + (cgrp << 2)] = vacc;
    }
    __syncthreads();                         // SYNC_F

    // ---- combine 4 j-segment partials (conflict-free banks) + v write ----
    {
        int c = tid >> 3, i = tid & 7;
        int base = (i * 4) * 68 + i * 4 + c;
        float vsum = (vs[base] + vs[base + 68]) +
                     (vs[base + 136] + vs[base + 204]);
        vout[(size_t)b * CH * SQ + c * SQ + s0 + i] = vsum;
    }
}

extern "C" void kernel_launch(void* const* d_in, const int* in_sizes, int n_in,
                              void* d_out, int out_size) {
    (void)in_sizes; (void)n_in; (void)out_size;
    const float* x  = (const float*)d_in[0];
    const float* Wt = (const float*)d_in[1];
    const float* Wx = (const float*)d_in[2];
    const float* Wa = (const float*)d_in[3];
    // d_in[4] = Wa_b: cancels exactly in the softmax, unused
    const float* bh = (const float*)d_in[5];

    float* vout = (float*)d_out;                     // (B, C, S)
    float* aout = vout + (size_t)BS * CH * SQ;       // (B, S, S)

    fused_kernel<<<GRID, 512>>>(x, Wt, Wx, bh, Wa, vout, aout);
}

// round 14
// speedup vs baseline: 1.2257x; 1.1194x over previous
#include <cuda_runtime.h>
#include <cstdint>

#define BS 4
#define SQ 1024
#define CH 64
#define UN 32
#define TSPAN 72
#define GRID (BS * 128)
#define THREADS 256

__device__ float g_k[BS * SQ * UN];
__device__ unsigned g_flag[GRID];   // monotonic; +9 per block per launch

__device__ __forceinline__ float htanh(float x) {
    float y;
    asm("tanh.approx.f32 %0, %1;" : "=f"(y) : "f"(x));
    return y;
}

// shared pool (floats)
#define OFF_XTS  0                    // xts [72][64] swizzled = 4608
#define OFF_U1   4608                 // ph1: wts[32][68]+wxs[32][68]=4352
                                      // ph2: ks[72][32]=2304 + vs[8][68]=544
#define OFF_QS   (4608 + 4352)        // qs [8][32] = 256
#define OFF_AS   (OFF_QS + 256)       // a_s [8][64] = 512
#define OFF_WAS  (OFF_AS + 512)       // 32
#define SMEM_FLOATS (OFF_WAS + 32)    // 9760 floats = 39.0KB -> 5 blocks/SM

__global__ __launch_bounds__(THREADS, 5) void fused_kernel(
    const float* __restrict__ x,
    const float* __restrict__ Wt,
    const float* __restrict__ Wx,
    const float* __restrict__ bh,
    const float* __restrict__ wa,
    float* __restrict__ vout,
    float* __restrict__ aout)
{
    __shared__ __align__(16) float pool[SMEM_FLOATS];

    float* xts  = pool + OFF_XTS;   // [ti][c], stride 64, 16B XOR swizzle
    float* qs   = pool + OFF_QS;    // [r][u]
    float* was  = pool + OFF_WAS;

    int b = blockIdx.x >> 7;
    int sblk = blockIdx.x & 127;
    int s0 = sblk << 3;
    int tid = threadIdx.x;
    int wid = tid >> 5, ln = tid & 31;
    int tlo = s0 - 32;

    // ---- top: input LDG wave only (critical path to flag release) ----
    {
        float* wts = pool + OFF_U1;          // [u][c], stride 68 (odd 16B units)
        float* wxs = wts + UN * 68;
        const float4* wt4 = (const float4*)Wt;
        const float4* wx4 = (const float4*)Wx;
#pragma unroll
        for (int i = 0; i < 2; i++) {
            int l = tid + i * 256;
            int u = l >> 4, g = l & 15;
            *(float4*)&wts[u * 68 + g * 4] = wt4[l];
            *(float4*)&wxs[u * 68 + g * 4] = wx4[l];
        }
        if (tid < UN) was[tid] = wa[tid];

        int gq = tid & 7;
        const float* xbase = x + (size_t)b * CH * SQ;
#pragma unroll
        for (int half = 0; half < 2; half++) {
            int cc = (tid >> 3) + half * 32;
            int gb = cc >> 2, clo = cc & 3;
            const float* xb = xbase + cc * SQ;
            if (sblk >= 4 && sblk <= 123) {
                const float4* xb4 = (const float4*)(xb + tlo);   // tlo%4==0
#pragma unroll
                for (int f = 0; f < 3; f++) {
                    int fi = gq + f * 8;
                    if (fi < 18) {
                        float4 v = xb4[fi];
                        int t0 = fi << 2;
                        xts[(t0 + 0) * 64 + (((((t0 + 0) & 7) ^ gb) << 2) | clo)] = v.x;
                        xts[(t0 + 1) * 64 + (((((t0 + 1) & 7) ^ gb) << 2) | clo)] = v.y;
                        xts[(t0 + 2) * 64 + (((((t0 + 2) & 7) ^ gb) << 2) | clo)] = v.z;
                        xts[(t0 + 3) * 64 + (((((t0 + 3) & 7) ^ gb) << 2) | clo)] = v.w;
                    }
                }
            } else {
#pragma unroll
                for (int p = 0; p < 9; p++) {
                    int ti = p * 8 + gq;
                    int tc = min(max(tlo + ti, 0), SQ - 1);
                    xts[ti * 64 + (((gb ^ gq) << 2) | clo)] = xb[tc];  // ti&7==gq
                }
            }
        }
    }
    __syncthreads();                         // SYNC_A

    // ---- phase 1: warp w computes BOTH q and k for its row ss=wid ----
    {
        const float* wts = pool + OFF_U1;
        const float* wxs = wts + UN * 68;
        int ss = wid;
        const float4* xp  = (const float4*)&xts[(32 + ss) * 64];
        const float4* wtp = (const float4*)&wts[ln * 68];
        const float4* wxp = (const float4*)&wxs[ln * 68];
        float q0 = 0.f, q1 = 0.f, q2 = 0.f, q3 = 0.f;
        float k0 = 0.f, k1 = 0.f, k2 = 0.f, k3 = 0.f;
#pragma unroll
        for (int gg = 0; gg < 16; gg++) {    // stored (swizzled) group
            float4 x4 = xp[gg];              // broadcast
            int wg = (gg & 8) | ((gg & 7) ^ ss);
            float4 wt = wtp[wg];
            float4 wx = wxp[wg];
            q0 = fmaf(x4.x, wt.x, q0); q1 = fmaf(x4.y, wt.y, q1);
            q2 = fmaf(x4.z, wt.z, q2); q3 = fmaf(x4.w, wt.w, q3);
            k0 = fmaf(x4.x, wx.x, k0); k1 = fmaf(x4.y, wx.y, k1);
            k2 = fmaf(x4.z, wx.z, k2); k3 = fmaf(x4.w, wx.w, k3);
        }
        qs[ss * 32 + ln] = (q0 + q1) + (q2 + q3);
        g_k[((size_t)b * SQ + s0 + ss) * UN + ln] =
            (k0 + k1) + (k2 + k3) + bh[ln];  // bh folded
    }
    __syncthreads();                         // SYNC_B: k stored, wts free

    // ---- warp 0: release (9 adds) + 9-neighbor spin + full ks fill.
    //      warps 1-7: zero-fill the a rows (off the critical path). ----
    float* ks = pool + OFF_U1;               // [ti][u], stride 32, XOR swizzle
    float* vs = ks + TSPAN * 32;             // [r][c], stride 68
    if (wid == 0) {
        if (ln < 9) {
            __threadfence();                 // release own k stores
            unsigned v = atomicAdd(&g_flag[blockIdx.x], 1u);
            unsigned base = v - (v % 9u);    // 9*(launchN-1)
            int owner = min(max(sblk - 4 + ln, 0), 127);
            volatile unsigned* f = (volatile unsigned*)&g_flag[(b << 7) + owner];
            while (*f <= base) { }
            __threadfence();                 // acquire
        }
        __syncwarp();
        const float4* gk4 = (const float4*)g_k;
#pragma unroll
        for (int rep = 0; rep < 18; rep++) { // 576 float4 over 32 lanes
            int lin = ln + rep * 32;
            int ti = lin >> 3, gq = lin & 7;
            int tc = min(max(tlo + ti, 0), SQ - 1);
            *(float4*)&ks[ti * 32 + ((gq ^ (ti & 7)) << 2)] =
                gk4[((size_t)b * SQ + tc) * 8 + gq];
        }
    } else {
        float4 zz = make_float4(0.f, 0.f, 0.f, 0.f);
        float4* abase = (float4*)(aout + (((size_t)b * SQ + s0) << 10));
        for (int idx = tid - 32; idx < 2048; idx += 224)
            abase[idx] = zz;
    }
    __syncthreads();                         // SYNC_D: ks ready, zeros ordered

    // ---- scores: warp w = row r; lane handles j=ln and j=ln+32 ----
    int r = wid;
    int s = s0 + r;
    int t1 = s - 32 + ln;                    // valid iff >= 0
    int t2 = t1 + 32;                        // valid iff < SQ
    bool v1 = (t1 >= 0), v2 = (t2 < SQ);
    int ti1 = r + ln;                        // ti2 = ti1+32, same &7
    const float* kb1 = &ks[ti1 * 32];
    const float* kb2 = kb1 + 32 * 32;
    int sw = (ti1 & 7) << 2;

    const float4* qp = (const float4*)&qs[r * 32];
    const float4* wap = (const float4*)was;
    float acc1 = 0.f, acc2 = 0.f;
#pragma unroll
    for (int g = 0; g < 8; g++) {
        float4 q4 = qp[g];
        float4 w4 = wap[g];
        int go = (g << 2) ^ sw;
        float4 ka = *(const float4*)&kb1[go];
        float4 kb = *(const float4*)&kb2[go];
        acc1 = fmaf(w4.x, htanh(q4.x + ka.x), acc1);
        acc1 = fmaf(w4.y, htanh(q4.y + ka.y), acc1);
        acc1 = fmaf(w4.z, htanh(q4.z + ka.z), acc1);
        acc1 = fmaf(w4.w, htanh(q4.w + ka.w), acc1);
        acc2 = fmaf(w4.x, htanh(q4.x + kb.x), acc2);
        acc2 = fmaf(w4.y, htanh(q4.y + kb.y), acc2);
        acc2 = fmaf(w4.z, htanh(q4.z + kb.z), acc2);
        acc2 = fmaf(w4.w, htanh(q4.w + kb.w), acc2);
    }

    // warp-local softmax (no max-shift: scores bounded by sum|wa|, the
    // shift cancels except through eps -> rel err <= ~1.3e-5)
    float e1 = v1 ? __expf(acc1) : 0.f;
    float e2 = v2 ? __expf(acc2) : 0.f;
    float sm = e1 + e2;
#pragma unroll
    for (int o = 16; o > 0; o >>= 1) sm += __shfl_xor_sync(0xffffffffu, sm, o);
    float inv = __fdividef(1.f, sm + 1e-7f);
    float a1 = e1 * inv, a2 = e2 * inv;

    float* a_s = pool + OFF_AS;
    a_s[(r << 6) + ln] = a1;
    a_s[(r << 6) + 32 + ln] = a2;

    // a window write (zeros were stored before SYNC_D -> ordered)
    size_t arowoff = ((size_t)b * SQ + s) << 10;
    if (v1) aout[arowoff + t1] = a1;
    if (v2) aout[arowoff + t2] = a2;
    __syncwarp();                            // a_s visible warp-locally

    // ---- v pass: 32 lanes = 2 j-halves x 16 c-groups; warp-local a ----
    {
        int jh = ln >> 4, cgrp = ln & 15;
        float4 vacc = make_float4(0.f, 0.f, 0.f, 0.f);
        const float* arow_s = &a_s[(r << 6) + (jh << 5)];
#pragma unroll
        for (int q4i = 0; q4i < 8; q4i++) {
            float4 a4 = *(const float4*)&arow_s[q4i << 2];
            int jb = (jh << 5) + (q4i << 2);
#pragma unroll
            for (int ee = 0; ee < 4; ee++) {
                int row = r + jb + ee;
                float av = (ee == 0) ? a4.x : (ee == 1) ? a4.y
                         : (ee == 2) ? a4.z : a4.w;
                float4 x4 = *(const float4*)&xts[row * 64 +
                                                 ((cgrp ^ (row & 7)) << 2)];
                vacc.x = fmaf(av, x4.x, vacc.x);
                vacc.y = fmaf(av, x4.y, vacc.y);
                vacc.z = fmaf(av, x4.z, vacc.z);
                vacc.w = fmaf(av, x4.w, vacc.w);
            }
        }
        vacc.x += __shfl_xor_sync(0xffffffffu, vacc.x, 16);
        vacc.y += __shfl_xor_sync(0xffffffffu, vacc.y, 16);
        vacc.z += __shfl_xor_sync(0xffffffffu, vacc.z, 16);
        vacc.w += __shfl_xor_sync(0xffffffffu, vacc.w, 16);
        if (ln < 16)
            *(float4*)&vs[r * 68 + (cgrp << 2)] = vacc;
    }
    __syncthreads();                         // SYNC_F

    // ---- coalesced transposed v write: 512 outputs, 2 per thread ----
#pragma unroll
    for (int repc = 0; repc < 2; repc++) {
        int idx = tid + repc * 256;
        int c = idx >> 3, i = idx & 7;
        vout[(size_t)b * CH * SQ + c * SQ + s0 + i] = vs[i * 68 + c];
    }
}

extern "C" void kernel_launch(void* const* d_in, const int* in_sizes, int n_in,
                              void* d_out, int out_size) {
    (void)in_sizes; (void)n_in; (void)out_size;
    const float* x  = (const float*)d_in[0];
    const float* Wt = (const float*)d_in[1];
    const float* Wx = (const float*)d_in[2];
    const float* Wa = (const float*)d_in[3];
    // d_in[4] = Wa_b: cancels exactly in the softmax, unused
    const float* bh = (const float*)d_in[5];

    float* vout = (float*)d_out;                     // (B, C, S)
    float* aout = vout + (size_t)BS * CH * SQ;       // (B, S, S)

    fused_kernel<<<GRID, THREADS>>>(x, Wt, Wx, bh, Wa, vout, aout);
}